// round 6
// baseline (speedup 1.0000x reference)
#include <cuda_runtime.h>
#include <cstddef>

#define V 49688
#define D 128
#define B 16
#define N 100

// V*D/4 float4 elements per batch slice
#define VD4 (V * D / 4)   // 1,590,016 (divisible by 2: 795,008 pairs)
#define VD8 (VD4 / 2)     // float4-pairs per slice

// Kernel 1: broadcast W into all B output slices.
// Each thread handles TWO float4s of W (HBM once, L2-resident for the 16x
// reuse) and stores them to all 16 batch copies. Writes dominate (407 MB).
__global__ __launch_bounds__(256) void bcast_W_kernel(
    const float4* __restrict__ W4, float4* __restrict__ out4) {
    int idx = blockIdx.x * blockDim.x + threadIdx.x;
    if (idx >= VD8) return;
    int i0 = idx * 2;
    float4 w0 = W4[i0];
    float4 w1 = W4[i0 + 1];
    float4* p = out4 + i0;
#pragma unroll
    for (int b = 0; b < B; ++b) {
        p[0] = w0;
        p[1] = w1;
        p += VD4;
    }
}

// Kernel 2: overwrite the B*N updated rows.
// out[b, node, :] = (1 - alpha[node]) * W[node, :] + alpha[node] * x[pos, :]
// where pos is the node's position 0..N-1 (node_feats = x[:N], batch-independent).
// One block per (b, pos) row; 32 threads x float4 covers D=128.
__global__ __launch_bounds__(32) void gated_update_kernel(
    const int* __restrict__ nodes, const float* __restrict__ x,
    const float* __restrict__ W, const float* __restrict__ alpha,
    float* __restrict__ out) {
    int row = blockIdx.x;          // 0 .. B*N-1
    int b = row / N;
    int pos = row % N;
    int node = nodes[b * N + pos];
    float a = alpha[node];
    float one_minus_a = 1.0f - a;

    int t = threadIdx.x;           // 0..31
    const float4* wr = (const float4*)(W + (size_t)node * D);
    const float4* xr = (const float4*)(x + (size_t)pos * D);
    float4* orow = (float4*)(out + (size_t)b * V * D + (size_t)node * D);

    float4 w = wr[t];
    float4 xv = xr[t];
    float4 r;
    r.x = one_minus_a * w.x + a * xv.x;
    r.y = one_minus_a * w.y + a * xv.y;
    r.z = one_minus_a * w.z + a * xv.z;
    r.w = one_minus_a * w.w + a * xv.w;
    orow[t] = r;
}

extern "C" void kernel_launch(void* const* d_in, const int* in_sizes, int n_in,
                              void* d_out, int out_size) {
    const int*   nodes = (const int*)d_in[0];    // (B, N) int32
    const float* x     = (const float*)d_in[1];  // (B*N, D) f32 (only first N rows used)
    const float* W     = (const float*)d_in[2];  // (V, D) f32
    const float* alpha = (const float*)d_in[3];  // (V, 1) f32
    float* out = (float*)d_out;                  // (B, V, D) f32

    // 1) broadcast W -> out[b] for all b
    int threads = 256;
    int blocks = (VD8 + threads - 1) / threads;  // 3106 blocks
    bcast_W_kernel<<<blocks, threads>>>((const float4*)W, (float4*)out);

    // 2) overwrite the B*N gated rows (stream-ordered after the broadcast)
    gated_update_kernel<<<B * N, 32>>>(nodes, x, W, alpha, out);
}

// round 8
// speedup vs baseline: 1.0247x; 1.0247x over previous
#include <cuda_runtime.h>
#include <cstddef>
#include <cstdint>

#define V 49688
#define D 128
#define B 16
#define N 100

#define VD4 (V * D / 4)          // float4s per batch slice = 1,590,016
#define ROWS_PER_BLK 16          // 256 threads, 16 threads/row, 8 floats/thread
#define NBLOCKS ((V + ROWS_PER_BLK - 1) / ROWS_PER_BLK)   // 3106

// One fused kernel.
// Block r owns rows [16r, 16r+16) of ALL 16 batch slices.
// Phase 1: scan nodes (B*N = 1600 ints) for hits in this row range -> SMEM
//          table tab[local_row][b] = pos+1 (0 = untouched).
// Phase 2: each thread owns 8 floats (2 float4) of one row; loads W once into
//          registers, checks its row's 16-byte tab entry with one LDS.128:
//          all-zero (99.97% of rows) -> 16x2 pure STG.128;
//          else per-batch gated value (1-a)*w + a*x[pos].
__global__ __launch_bounds__(256) void fused_gated_bcast_kernel(
    const int* __restrict__ nodes,    // (B, N)
    const float* __restrict__ x,      // (B*N, D), only rows [0,N) used
    const float* __restrict__ W,      // (V, D)
    const float* __restrict__ alpha,  // (V, 1)
    float* __restrict__ out) {        // (B, V, D)

    __shared__ __align__(16) uint8_t tab[ROWS_PER_BLK][B];  // 256 bytes

    const int tid = threadIdx.x;
    const int row0 = blockIdx.x * ROWS_PER_BLK;

    // zero the table (64 threads x uint32 = 256B)
    if (tid < 64) ((uint32_t*)tab)[tid] = 0u;
    __syncthreads();

    // scan the 1600 node entries for rows in [row0, row0+16)
    for (int i = tid; i < B * N; i += 256) {
        int node = nodes[i];
        unsigned local = (unsigned)(node - row0);
        if (local < ROWS_PER_BLK) {
            tab[local][i / N] = (uint8_t)((i % N) + 1);
        }
    }
    __syncthreads();

    const int local_row = tid >> 4;          // 0..15
    const int v = row0 + local_row;
    if (v >= V) return;
    const int col = (tid & 15) * 8;          // float offset within row, 0..120

    // load this thread's 8 W floats once
    const float4* wp = (const float4*)(W + (size_t)v * D + col);
    float4 w0 = wp[0];
    float4 w1 = wp[1];

    // one LDS.128: the 16 batch flags for this row
    uint4 flags = *(const uint4*)tab[local_row];

    float4* p = (float4*)(out + (size_t)v * D + col);   // batch 0 slot

    if ((flags.x | flags.y | flags.z | flags.w) == 0u) {
        // fast path: identical copy to all 16 batches
#pragma unroll
        for (int b = 0; b < B; ++b) {
            p[0] = w0;
            p[1] = w1;
            p += VD4;
        }
    } else {
        const uint8_t* f = tab[local_row];
        float a = 0.0f, oma = 1.0f;
        // alpha is per-row; load once if any batch patches this row
        a = alpha[v];
        oma = 1.0f - a;
#pragma unroll
        for (int b = 0; b < B; ++b) {
            uint8_t t = f[b];
            if (t == 0) {
                p[0] = w0;
                p[1] = w1;
            } else {
                int pos = (int)t - 1;
                const float4* xp = (const float4*)(x + (size_t)pos * D + col);
                float4 x0 = xp[0];
                float4 x1 = xp[1];
                float4 r0, r1;
                r0.x = oma * w0.x + a * x0.x;
                r0.y = oma * w0.y + a * x0.y;
                r0.z = oma * w0.z + a * x0.z;
                r0.w = oma * w0.w + a * x0.w;
                r1.x = oma * w1.x + a * x1.x;
                r1.y = oma * w1.y + a * x1.y;
                r1.z = oma * w1.z + a * x1.z;
                r1.w = oma * w1.w + a * x1.w;
                p[0] = r0;
                p[1] = r1;
            }
            p += VD4;
        }
    }
}

extern "C" void kernel_launch(void* const* d_in, const int* in_sizes, int n_in,
                              void* d_out, int out_size) {
    const int*   nodes = (const int*)d_in[0];    // (B, N) int32
    const float* x     = (const float*)d_in[1];  // (B*N, D) f32
    const float* W     = (const float*)d_in[2];  // (V, D) f32
    const float* alpha = (const float*)d_in[3];  // (V, 1) f32
    float* out = (float*)d_out;                  // (B, V, D) f32

    fused_gated_bcast_kernel<<<NBLOCKS, 256>>>(nodes, x, W, alpha, out);
}

// round 9
// speedup vs baseline: 1.5106x; 1.4743x over previous
#include <cuda_runtime.h>
#include <cstddef>
#include <cstdint>

#define V 49688
#define D 128
#define B 16
#define N 100

#define RPB 64                              // W rows staged per block
#define NBLOCKS ((V + RPB - 1) / RPB)       // 777
#define VD ((size_t)V * D)                  // floats per batch slice

__device__ __forceinline__ uint32_t smem_u32(const void* p) {
    uint32_t a;
    asm("{ .reg .u64 t; cvta.to.shared.u64 t, %1; cvt.u32.u64 %0, t; }"
        : "=r"(a) : "l"(p));
    return a;
}

// One block: stage rows [row0, row0+nrows) of W in SMEM, bulk-store the tile
// to all 16 batch slices via TMA (L1 bypassed), then patch gated rows.
__global__ __launch_bounds__(256) void fused_tma_bcast_kernel(
    const int* __restrict__ nodes,    // (B, N)
    const float* __restrict__ x,      // (B*N, D), rows [0,N) used (node_feats)
    const float* __restrict__ W,      // (V, D)
    const float* __restrict__ alpha,  // (V, 1)
    float* __restrict__ out) {        // (B, V, D)

    __shared__ __align__(128) float tile[RPB * D];        // 32 KB
    __shared__ __align__(16) uint8_t tab[RPB][B];         // 1 KB

    const int tid = threadIdx.x;
    const int row0 = blockIdx.x * RPB;
    const int nrows = min(RPB, V - row0);

    // zero patch table: RPB*B/4 = 256 words, one per thread
    ((uint32_t*)tab)[tid] = 0u;
    __syncthreads();

    // scan the 1600 node entries for rows owned by this block
    for (int i = tid; i < B * N; i += 256) {
        int node = nodes[i];
        unsigned local = (unsigned)(node - row0);
        if (local < (unsigned)nrows) {
            tab[local][i / N] = (uint8_t)((i % N) + 1);
        }
    }

    // stage W tile into SMEM (coalesced float4)
    const float4* wsrc = (const float4*)(W + (size_t)row0 * D);
    float4* tdst = (float4*)tile;
    const int n4 = nrows * (D / 4);          // up to 2048 float4s
    for (int j = tid; j < n4; j += 256) {
        tdst[j] = wsrc[j];
    }

    // make generic-proxy SMEM writes visible to the async proxy, then sync
    asm volatile("fence.proxy.async.shared::cta;" ::: "memory");
    __syncthreads();

    // one thread issues 16 bulk stores SMEM -> each batch slice (bypasses L1)
    if (tid == 0) {
        uint32_t saddr = smem_u32(tile);
        uint32_t bytes = (uint32_t)(nrows * D * sizeof(float));
#pragma unroll
        for (int b = 0; b < B; ++b) {
            const float* dst = out + (size_t)b * VD + (size_t)row0 * D;
            asm volatile(
                "cp.async.bulk.global.shared::cta.bulk_group [%0], [%1], %2;"
                :: "l"(dst), "r"(saddr), "r"(bytes) : "memory");
        }
        asm volatile("cp.async.bulk.commit_group;" ::: "memory");
        asm volatile("cp.async.bulk.wait_group 0;" ::: "memory");
    }
    __syncthreads();   // bulk stores globally visible before patches

    // patch gated rows: out[b, v, :] = (1-a)*W[v,:] + a*x[pos,:]
    // 16 threads per row, 4 passes cover 64 rows.
    const int col = (tid & 15) * 8;          // float offset, 0..120
#pragma unroll
    for (int lrb = 0; lrb < RPB; lrb += 16) {
        int lr = lrb + (tid >> 4);
        if (lr >= nrows) continue;
        uint4 fl = *(const uint4*)tab[lr];
        if ((fl.x | fl.y | fl.z | fl.w) == 0u) continue;

        int v = row0 + lr;
        float a = alpha[v];
        float oma = 1.0f - a;
        const float4* wp = (const float4*)(tile + lr * D + col);
        float4 w0 = wp[0];
        float4 w1 = wp[1];
        const uint8_t* f = tab[lr];
#pragma unroll
        for (int b = 0; b < B; ++b) {
            uint8_t t = f[b];
            if (t == 0) continue;
            int pos = (int)t - 1;
            const float4* xp = (const float4*)(x + (size_t)pos * D + col);
            float4 x0 = xp[0];
            float4 x1 = xp[1];
            float4 r0, r1;
            r0.x = oma * w0.x + a * x0.x;  r0.y = oma * w0.y + a * x0.y;
            r0.z = oma * w0.z + a * x0.z;  r0.w = oma * w0.w + a * x0.w;
            r1.x = oma * w1.x + a * x1.x;  r1.y = oma * w1.y + a * x1.y;
            r1.z = oma * w1.z + a * x1.z;  r1.w = oma * w1.w + a * x1.w;
            float4* p = (float4*)(out + (size_t)b * VD + (size_t)v * D + col);
            p[0] = r0;
            p[1] = r1;
        }
    }
}

extern "C" void kernel_launch(void* const* d_in, const int* in_sizes, int n_in,
                              void* d_out, int out_size) {
    const int*   nodes = (const int*)d_in[0];    // (B, N) int32
    const float* x     = (const float*)d_in[1];  // (B*N, D) f32
    const float* W     = (const float*)d_in[2];  // (V, D) f32
    const float* alpha = (const float*)d_in[3];  // (V, 1) f32
    float* out = (float*)d_out;                  // (B, V, D) f32

    fused_tma_bcast_kernel<<<NBLOCKS, 256>>>(nodes, x, W, alpha, out);
}